// round 5
// baseline (speedup 1.0000x reference)
#include <cuda_runtime.h>
#include <math.h>
#include <stdint.h>

#define NB 256
#define NI 512   // outputs (i)
#define NJ 512   // inputs  (j) -> contraction K
#define NW 64

// Scratch (static device arrays: allocation rules OK)
__device__ float g_inT  [(size_t)NW * NB * NJ];   // [w][b][j]  33.5 MB
__device__ float g_dropT[(size_t)NW * NI * NJ];   // [w][i][j]  67   MB
__device__ float g_outT [(size_t)NW * NB * NI];   // [w][b][i]  33.5 MB

__device__ __forceinline__ float tf32r(float x) {
    uint32_t u; asm("cvt.rna.tf32.f32 %0, %1;" : "=r"(u) : "f"(x));
    return __uint_as_float(u);
}

// ---------------------------------------------------------------------------
// Kernel 1: dropT[w][i][j], tf32-rounded.
// denom2 = 1 - 2 at cos + at^2.  Kerr term (~2.7e-19 rad) below fp32 eps.
// ---------------------------------------------------------------------------
__global__ void __launch_bounds__(256) dropT_kernel(
        const float* __restrict__ phase_shift,
        const float* __restrict__ coupling) {
    const int j = blockIdx.x * 256 + threadIdx.x;
    const int i = blockIdx.y;
    const int k = i * NJ + j;

    const double WLMIN = 1.53e-06, WLMAX = 1.57e-06;
    double c    = WLMIN + (WLMAX - WLMIN) * ((double)k / (double)(NI * NJ));
    double pref = (4.0 * M_PI * M_PI * 4.2 * 5e-06) / (c * c);   // 2*pi/fsr
    const float base = (float)(pref * (WLMIN - c)) + phase_shift[k];
    const float dphi = (float)(pref * ((WLMAX - WLMIN) / 63.0));

    float kap = fminf(fmaxf(coupling[k], 0.1f), 0.9f);
    float t   = sqrtf(1.0f - kap * kap);
    const float alpha = (float)(1.0 - M_PI / 15000.0);
    float at  = alpha * t;
    const float A2    = 1.0f + at * at;
    const float twoAt = 2.0f * at;
    const float coef  = kap * kap * alpha;

    float* dst = g_dropT + (size_t)i * NJ + j;
#pragma unroll 4
    for (int w = 0; w < NW; w++) {
        float ph = fmaf((float)w, dphi, base);
        float d  = __fdividef(coef, A2 - twoAt * cosf(ph));
        dst[(size_t)w * NI * NJ] = tf32r(d);
    }
}

// ---------------------------------------------------------------------------
// Kernel 2: transpose input [b][j][w] -> inT[w][b][j], tf32-rounded.
// ---------------------------------------------------------------------------
__global__ void __launch_bounds__(256) tin_kernel(const float* __restrict__ in) {
    __shared__ float s[32][65];
    const int b  = blockIdx.y;
    const int j0 = blockIdx.x * 32;
    const int t  = threadIdx.x;

    {   // load 32 j-rows x 64 w
        int r = t >> 3, wq = (t & 7) * 8;
        const float4* src = (const float4*)(in + ((size_t)b * NJ + j0 + r) * NW + wq);
        float4 v0 = src[0], v1 = src[1];
        s[r][wq + 0] = v0.x; s[r][wq + 1] = v0.y; s[r][wq + 2] = v0.z; s[r][wq + 3] = v0.w;
        s[r][wq + 4] = v1.x; s[r][wq + 5] = v1.y; s[r][wq + 6] = v1.z; s[r][wq + 7] = v1.w;
    }
    __syncthreads();
    {   // write 64 w-rows x 32 j
        int w = t >> 2, jg = (t & 3) * 8;
        float* dst = g_inT + ((size_t)w * NB + b) * NJ + j0 + jg;
        float4 o0, o1;
        o0.x = tf32r(s[jg + 0][w]); o0.y = tf32r(s[jg + 1][w]);
        o0.z = tf32r(s[jg + 2][w]); o0.w = tf32r(s[jg + 3][w]);
        o1.x = tf32r(s[jg + 4][w]); o1.y = tf32r(s[jg + 5][w]);
        o1.z = tf32r(s[jg + 6][w]); o1.w = tf32r(s[jg + 7][w]);
        ((float4*)dst)[0] = o0; ((float4*)dst)[1] = o1;
    }
}

// ---------------------------------------------------------------------------
// Kernel 3: mma.sync tf32 GEMM per w-plane, ldmatrix fragment loads.
// CTA: 128 threads = 4 warps (2x2), tile 128(b) x 128(i), warp tile 64x64.
// Kc=32, double-buffered cp.async.  RS=36 padding -> LDSM conflict-free.
// ---------------------------------------------------------------------------
#define TM 128
#define TN 128
#define KC 32
#define NCH (NJ / KC)          // 16
#define RS 36                  // smem row stride (floats)
#define TILE_F (128 * RS)      // floats per tile
#define TILE_B (TILE_F * 4)    // 18432 bytes
#define SMEM_REQ (4 * TILE_B)  // 73728 bytes

#define CPA(s, g) asm volatile("cp.async.cg.shared.global [%0], [%1], 16;" :: "r"(s), "l"(g))

#define LDSM4(r, addr) \
    asm volatile("ldmatrix.sync.aligned.m8n8.x4.shared.b16 {%0,%1,%2,%3}, [%4];" \
        : "=r"((r)[0]), "=r"((r)[1]), "=r"((r)[2]), "=r"((r)[3]) : "r"(addr))

#define MMA_TF32(c, a0, a1, a2, a3, b0, b1) \
    asm volatile("mma.sync.aligned.m16n8k8.row.col.f32.tf32.tf32.f32 " \
        "{%0,%1,%2,%3}, {%4,%5,%6,%7}, {%8,%9}, {%0,%1,%2,%3};" \
        : "+f"((c)[0]), "+f"((c)[1]), "+f"((c)[2]), "+f"((c)[3]) \
        : "r"(a0), "r"(a1), "r"(a2), "r"(a3), "r"(b0), "r"(b1))

static __device__ __forceinline__ uint32_t smem_u32(const void* p) {
    uint32_t a;
    asm("{ .reg .u64 t; cvta.to.shared.u64 t, %1; cvt.u32.u64 %0, t; }" : "=r"(a) : "l"(p));
    return a;
}

__global__ void __launch_bounds__(128) gemm_kernel() {
    extern __shared__ float smem[];          // [A0|A1|B0|B1]
    const uint32_t sbase = smem_u32(smem);

    const int tid = threadIdx.x;
    const int w   = blockIdx.x;
    const int b0  = blockIdx.y * TM;
    const int i0  = blockIdx.z * TN;

    // ---- loaders: thread t stages rows (t>>3)+16u, word t&7, u=0..7, per tile
    const int lrow0 = tid >> 3, lwc = tid & 7;
    const float* gA = g_inT   + ((size_t)w * NB + b0 + lrow0) * NJ + lwc * 4;
    const float* gB = g_dropT + ((size_t)w * NI + i0 + lrow0) * NJ + lwc * 4;
    const uint32_t so0 = (uint32_t)(lrow0 * RS * 4 + lwc * 16);

#define STAGE(bufA, bufB, ga, gb) do { \
    _Pragma("unroll") \
    for (int u = 0; u < 8; u++) { \
        CPA((bufA) + so0 + u * (16 * RS * 4), (ga) + (size_t)u * 16 * NJ); \
        CPA((bufB) + so0 + u * (16 * RS * 4), (gb) + (size_t)u * 16 * NJ); \
    } \
    asm volatile("cp.async.commit_group;" ::: "memory"); \
} while (0)

    // prologue: chunk 0 -> buf0, chunk 1 -> buf1
    STAGE(sbase,              sbase + 2 * TILE_B, gA,      gB);
    STAGE(sbase + TILE_B,     sbase + 3 * TILE_B, gA + KC, gB + KC);
    gA += 2 * KC; gB += 2 * KC;

    // ---- fragment indexing ----
    const int lane = tid & 31, wid = tid >> 5;
    const int g = lane >> 2, q = lane & 3;
    const int wm = (wid >> 1) * 64;      // warp m-offset (0/64)
    const int wn = (wid & 1) * 64;       // warp n-offset (0/64)
    // ldmatrix lane row/col offset (floats): rows 0-15 via lanes&15, +4 cols for hi half
    const uint32_t LA = (uint32_t)((lane & 15) * RS + (lane >> 4) * 4) * 4;

    float acc[4][8][4];
#pragma unroll
    for (int mt = 0; mt < 4; mt++)
#pragma unroll
        for (int nt = 0; nt < 8; nt++)
#pragma unroll
            for (int r = 0; r < 4; r++) acc[mt][nt][r] = 0.0f;

    for (int c = 0; c < NCH; c++) {
        if (c < NCH - 1) asm volatile("cp.async.wait_group 1;" ::: "memory");
        else             asm volatile("cp.async.wait_group 0;" ::: "memory");
        __syncthreads();

        const int par = c & 1;
        const uint32_t pA = sbase + par * TILE_B + LA;
        const uint32_t pB = sbase + (2 + par) * TILE_B + LA;

#pragma unroll
        for (int ks = 0; ks < 4; ks++) {
            const uint32_t k0 = ks * 8 * 4;   // bytes
            uint32_t a[4][4], b[4][4];
#pragma unroll
            for (int mt = 0; mt < 4; mt++)
                LDSM4(a[mt], pA + (uint32_t)((wm + mt * 16) * RS * 4) + k0);
#pragma unroll
            for (int np = 0; np < 4; np++)
                LDSM4(b[np], pB + (uint32_t)((wn + np * 16) * RS * 4) + k0);
#pragma unroll
            for (int mt = 0; mt < 4; mt++)
#pragma unroll
                for (int np = 0; np < 4; np++) {
                    MMA_TF32(acc[mt][2 * np],     a[mt][0], a[mt][1], a[mt][2], a[mt][3],
                             b[np][0], b[np][2]);
                    MMA_TF32(acc[mt][2 * np + 1], a[mt][0], a[mt][1], a[mt][2], a[mt][3],
                             b[np][1], b[np][3]);
                }
        }

        if (c + 2 < NCH) {
            __syncthreads();   // all warps done reading buf[par]
            STAGE(sbase + par * TILE_B, sbase + (2 + par) * TILE_B, gA, gB);
            gA += KC; gB += KC;
        }
    }

    // ---- epilogue: acc -> g_outT[w][b][i] (8B stores) ----
#pragma unroll
    for (int mt = 0; mt < 4; mt++) {
        const int row = b0 + wm + mt * 16 + g;
#pragma unroll
        for (int nt = 0; nt < 8; nt++) {
            const int col = i0 + wn + nt * 8 + 2 * q;
            float2 v0 = make_float2(acc[mt][nt][0], acc[mt][nt][1]);
            float2 v1 = make_float2(acc[mt][nt][2], acc[mt][nt][3]);
            *(float2*)&g_outT[((size_t)w * NB + row)     * NI + col] = v0;
            *(float2*)&g_outT[((size_t)w * NB + row + 8) * NI + col] = v1;
        }
    }
}

// ---------------------------------------------------------------------------
// Kernel 4: transpose outT[w][b][i] -> out[b][i][w]
// ---------------------------------------------------------------------------
__global__ void __launch_bounds__(256) tout_kernel(float* __restrict__ out) {
    __shared__ float s[32][65];
    const int b  = blockIdx.y;
    const int i0 = blockIdx.x * 32;
    const int t  = threadIdx.x;

    {   // load 64 w-rows x 32 i
        int w = t >> 2, ig = (t & 3) * 8;
        const float4* src = (const float4*)(g_outT + ((size_t)w * NB + b) * NI + i0 + ig);
        float4 v0 = src[0], v1 = src[1];
        s[ig + 0][w] = v0.x; s[ig + 1][w] = v0.y; s[ig + 2][w] = v0.z; s[ig + 3][w] = v0.w;
        s[ig + 4][w] = v1.x; s[ig + 5][w] = v1.y; s[ig + 6][w] = v1.z; s[ig + 7][w] = v1.w;
    }
    __syncthreads();
    {   // write 32 i-rows x 64 w (256B per row)
        int r = t >> 3, wq = (t & 7) * 8;
        float* dst = out + ((size_t)b * NI + i0 + r) * NW + wq;
        float4 o0, o1;
        o0.x = s[r][wq + 0]; o0.y = s[r][wq + 1]; o0.z = s[r][wq + 2]; o0.w = s[r][wq + 3];
        o1.x = s[r][wq + 4]; o1.y = s[r][wq + 5]; o1.z = s[r][wq + 6]; o1.w = s[r][wq + 7];
        ((float4*)dst)[0] = o0; ((float4*)dst)[1] = o1;
    }
}

// ---------------------------------------------------------------------------
extern "C" void kernel_launch(void* const* d_in, const int* in_sizes, int n_in,
                              void* d_out, int out_size) {
    const float* input    = (const float*)d_in[0];  // [256,512,64]
    const float* phase    = (const float*)d_in[1];  // [512,512]
    const float* coupling = (const float*)d_in[2];  // [512,512]
    float* out            = (float*)d_out;          // [256,512,64]

    cudaFuncSetAttribute(gemm_kernel, cudaFuncAttributeMaxDynamicSharedMemorySize, SMEM_REQ);

    dropT_kernel<<<dim3(NJ / 256, NI), 256>>>(phase, coupling);
    tin_kernel  <<<dim3(NJ / 32, NB), 256>>>(input);
    gemm_kernel <<<dim3(NW, NB / TM, NI / TN), 128, SMEM_REQ>>>();
    tout_kernel <<<dim3(NI / 32, NB), 256>>>(out);
}